// round 12
// baseline (speedup 1.0000x reference)
#include <cuda_runtime.h>
#include <math.h>
#include <stdint.h>

#define NSNR 2048
#define NT   4096
#define NP   100
#define NI   99
#define TPB  256
#define NC   (NT / 4)      // 1024 chunks of 4 elements
#define CPT  (NC / TPB)    // 4 chunks per thread
#define NWARP (TPB / 32)
#define NACC 32
#define BHW  12            // inverse band half-width (r^13 ~ 3.6e-8)
#define BW   (2 * BHW + 1) // 25

__device__ double       g_acc[NACC];   // zero-init; reset by last row each run
__device__ unsigned int g_ticket;      // self-resetting via atomicInc wrap

// ---------------------------------------------------------------------------
// Banded rows of inv(tri(1,4,1)) (n=98), compile-time double Thomas.
// Stored transposed: w[d][i] = inv[i][i + d - BHW].
// ---------------------------------------------------------------------------
struct WT { float w[BW][NP]; };
static constexpr WT make_wt() {
    WT out{};
    for (int i = 0; i < 98; i++) {
        double cp[98] = {}, dp[98] = {};
        double c = 0.25;
        cp[0] = c;
        dp[0] = (i == 0 ? 1.0 : 0.0) * 0.25;
        for (int j = 1; j < 98; j++) {
            c = 1.0 / (4.0 - cp[j - 1]);
            cp[j] = c;
            double r = (j == i ? 1.0 : 0.0);
            dp[j] = (r - dp[j - 1]) * c;
        }
        double x = dp[97];
        {
            int d = 97 - i + BHW;
            if (d >= 0 && d < BW) out.w[d][i] = (float)x;
        }
        for (int j = 96; j >= 0; j--) {
            x = dp[j] - cp[j] * x;
            int d = j - i + BHW;
            if (d >= 0 && d < BW) out.w[d][i] = (float)x;
        }
    }
    return out;
}
__device__ constexpr WT d_wt = make_wt();

// Block-wide exclusive scan of one float per thread. Contains __syncthreads.
__device__ __forceinline__ float block_scan_excl(float v, float* warp_sums, float* total) {
    int lane = threadIdx.x & 31, wid = threadIdx.x >> 5;
    float x = v;
#pragma unroll
    for (int o = 1; o < 32; o <<= 1) {
        float y = __shfl_up_sync(0xffffffffu, x, o);
        if (lane >= o) x += y;
    }
    if (lane == 31) warp_sums[wid] = x;
    __syncthreads();
    if (wid == 0) {
        float w = (lane < NWARP) ? warp_sums[lane] : 0.0f;
#pragma unroll
        for (int o = 1; o < NWARP; o <<= 1) {
            float y = __shfl_up_sync(0xffffffffu, w, o);
            if (lane >= o) w += y;
        }
        if (lane < NWARP) warp_sums[lane] = w;
    }
    __syncthreads();
    float excl = (x - v) + (wid ? warp_sums[wid - 1] : 0.0f);
    *total = warp_sums[NWARP - 1];
    return excl;
}

// ---------------------------------------------------------------------------
__global__ void __launch_bounds__(TPB, 7) wasserstein_kernel(
    const float* __restrict__ f, const float* __restrict__ obs,
    const float* __restrict__ t, float* __restrict__ out)
{
    __shared__ float  sCDF[NT];          // obs CDF for search (16 KB)
    __shared__ float  sCh[NC];           // chunk sums / prefixes (4 KB)
    __shared__ float4 scf4[NP];          // u-domain spline coeffs
    __shared__ float  sQ[NP];
    __shared__ float  sM[NP];
    __shared__ float  srhs[98 + 2 * BHW];
    __shared__ float  warp_sums[NWARP];
    __shared__ float  red[NWARP];
    __shared__ float  sEnds[2];

    const int   row = blockIdx.x;
    const int   tid = threadIdx.x;
    const float dt  = t[1] - t[0];
    const float hd  = 0.5f * dt;

    if (tid < BHW) { srhs[tid] = 0.0f; srhs[98 + BHW + tid] = 0.0f; }

    float4 va[CPT];     // raw row values: obs during phase A, then reused for f
    float  pfx[CPT];
    float  Ptot;

    // ============ Phase A: obs -> CDF + chunk scan ============
    {
        const float4* src4 = reinterpret_cast<const float4*>(obs + (size_t)row * NT);
#pragma unroll
        for (int i = 0; i < CPT; i++) {
            float4 v = src4[tid + TPB * i];
            va[i] = v;
            sCh[tid + TPB * i] =
                ((fabsf(v.x) + fabsf(v.y)) + fabsf(v.z)) + fabsf(v.w);
        }
        if (tid == 0)       sEnds[0] = fabsf(va[0].x);
        if (tid == TPB - 1) sEnds[1] = fabsf(va[CPT - 1].w);
    }
    __syncthreads();
    {
        float4 g4 = reinterpret_cast<float4*>(sCh)[tid];
        float local = ((g4.x + g4.y) + g4.z) + g4.w;
        float excl = block_scan_excl(local, warp_sums, &Ptot);
        float4 p4;
        p4.x = excl; p4.y = p4.x + g4.x; p4.z = p4.y + g4.y; p4.w = p4.z + g4.z;
        reinterpret_cast<float4*>(sCh)[tid] = p4;
    }
    __syncthreads();
#pragma unroll
    for (int i = 0; i < CPT; i++) pfx[i] = sCh[tid + TPB * i];

    const float y0A = sEnds[0];
    const float totalA = dt * Ptot - hd * (y0A + sEnds[1]);

    // element CDF: S = base + hd*(r_k + r_{k-1})
#pragma unroll
    for (int i = 0; i < CPT; i++) {
        int c = tid + TPB * i;
        float base = dt * pfx[i] - hd * y0A;
        float4 o;
        float rprev = 0.0f, rr = fabsf(va[i].x);
        o.x = fmaf(hd, rr + rprev, base); rprev = rr; rr += fabsf(va[i].y);
        o.y = fmaf(hd, rr + rprev, base); rprev = rr; rr += fabsf(va[i].z);
        o.z = fmaf(hd, rr + rprev, base); rprev = rr; rr += fabsf(va[i].w);
        o.w = fmaf(hd, rr + rprev, base);
        reinterpret_cast<float4*>(sCDF)[c] = o;
    }
    __syncthreads();   // sCDF published; sCh/sEnds free; va (obs) dead

    // ---- EARLY ISSUE of the f row LDGs: latency hides behind the search ----
    {
        const float4* src4 = reinterpret_cast<const float4*>(f + (size_t)row * NT);
#pragma unroll
        for (int i = 0; i < CPT; i++) va[i] = src4[tid + TPB * i];
    }

    // inverse CDF at 100 quantiles (interpolation + bisection hybrid)
    if (tid < NP) {
        float target = ((float)tid / 99.0f) * totalA;
        int lo = 0, hi = NT - 1;
        float Slo = 0.0f, Shi = totalA;
        int iter = 0;
        while (hi - lo > 1) {
            int mid;
            float den = Shi - Slo;
            if ((iter & 1) == 0 && den > 0.0f) {
                float frac = (target - Slo) / den;
                mid = lo + 1 + (int)(frac * (float)(hi - lo - 1));
                mid = min(max(mid, lo + 1), hi - 1);
            } else {
                mid = (lo + hi) >> 1;
            }
            float Sm = sCDF[mid];
            if (Sm <= target) { lo = mid; Slo = Sm; }
            else              { hi = mid; Shi = Sm; }
            iter++;
        }
        if (sCDF[hi] <= target) lo = hi;
        int j = min(lo, NT - 2);
        float Sj  = sCDF[j];
        float den = sCDF[j + 1] - Sj;
        float q = (float)j * dt;
        if (den > 0.0f) q += (target - Sj) * dt / den;
        sQ[tid] = q;
    }

    // f chunk sums (LDG data arrived behind the search)
#pragma unroll
    for (int i = 0; i < CPT; i++)
        sCh[tid + TPB * i] =
            ((fabsf(va[i].x) + fabsf(va[i].y)) + fabsf(va[i].z)) + fabsf(va[i].w);
    if (tid == 0)       sEnds[0] = fabsf(va[0].x);
    if (tid == TPB - 1) sEnds[1] = fabsf(va[CPT - 1].w);
    __syncthreads();   // publishes sQ, sCh, sEnds

    // rhs for natural cubic spline (98 interior rows)
    if (tid < 98) {
        const float S6 = 6.0f * 9801.0f;   // 6 / h^2
        srhs[BHW + tid] = S6 * (sQ[tid + 2] - 2.0f * sQ[tid + 1] + sQ[tid]);
    }
    __syncthreads();

    // banded-inverse parallel solve
    if (tid < 98) {
        float m = 0.0f;
#pragma unroll
        for (int d = 0; d < BW; d++)
            m = fmaf(d_wt.w[d][tid], srhs[tid + d], m);
        sM[tid + 1] = m;
    }
    if (tid == 98) sM[0] = 0.0f;
    if (tid == 99) sM[NP - 1] = 0.0f;
    __syncthreads();

    // u-domain spline coefficients: val = a + du*(b' + du*(c' + du*d')),
    // du = u - idx, u = S * (99/T)  (b'=bH, c'=cH^2, d'=dH^3)
    if (tid < NI) {
        const float H2 = 1.0f / 9801.0f;
        float Mi = sM[tid], Mi1 = sM[tid + 1];
        float4 c;
        c.x = sQ[tid];
        c.y = (sQ[tid + 1] - sQ[tid]) - H2 * (2.0f * Mi + Mi1) * (1.0f / 6.0f);
        c.z = Mi * 0.5f * H2;
        c.w = (Mi1 - Mi) * H2 * (1.0f / 6.0f);
        scf4[tid] = c;
    }
    // (visibility of scf4 is covered by block_scan_excl's internal barriers)

    // ---- phase B scan over f chunk sums ----
    {
        float4 g4 = reinterpret_cast<float4*>(sCh)[tid];
        float local = ((g4.x + g4.y) + g4.z) + g4.w;
        float excl = block_scan_excl(local, warp_sums, &Ptot);
        float4 p4;
        p4.x = excl; p4.y = p4.x + g4.x; p4.z = p4.y + g4.y; p4.w = p4.z + g4.z;
        reinterpret_cast<float4*>(sCh)[tid] = p4;
    }
    __syncthreads();
#pragma unroll
    for (int i = 0; i < CPT; i++) pfx[i] = sCh[tid + TPB * i];

    const float y0B = sEnds[0];
    const float totalB = dt * Ptot - hd * (y0B + sEnds[1]);
    const float invT   = 1.0f / totalB;
    const float invT99 = 99.0f * invT;

    // ---- eval loop: invT factored out of the sum ----
    float gsum = 0.0f;
    float gFirst = 0.0f, gLast = 0.0f;
#pragma unroll
    for (int i = 0; i < CPT; i++) {
        int c = tid + TPB * i;
        float base = dt * pfx[i] - hd * y0B;
        float rprev = 0.0f, rr = 0.0f;
        float av[4] = { fabsf(va[i].x), fabsf(va[i].y), fabsf(va[i].z), fabsf(va[i].w) };
#pragma unroll
        for (int k = 0; k < 4; k++) {
            int j = 4 * c + k;
            rr += av[k];
            float S = fmaf(hd, rr + rprev, base);
            rprev = rr;

            float u = fminf(S * invT99, 99.0f);
            int idx = min((int)u, NI - 1);
            float du = u - (float)idx;
            float4 cf = scf4[idx];
            float val = cf.x + du * (cf.y + du * (cf.z + du * cf.w));
            float diff = (float)j * dt - val;
            float g = diff * diff * av[k];
            gsum += g;
            if (i == 0 && k == 0) gFirst = g;        // j==0 (tid==0 only)
            if (i == CPT - 1 && k == 3) gLast = g;   // j==NT-1 (tid==255 only)
        }
    }
    if (tid == 0)       gsum -= 0.5f * gFirst;
    if (tid == TPB - 1) gsum -= 0.5f * gLast;

#pragma unroll
    for (int o = 16; o; o >>= 1) gsum += __shfl_down_sync(0xffffffffu, gsum, o);
    if ((tid & 31) == 0) red[tid >> 5] = gsum;
    __syncthreads();

    if (tid == 0) {
        float s = 0.0f;
#pragma unroll
        for (int w = 0; w < NWARP; w++) s += red[w];
        double my = (double)(dt * invT * s);
        atomicAdd(&g_acc[row & (NACC - 1)], my);
        __threadfence();
        unsigned tk = atomicInc(&g_ticket, NSNR - 1);   // wraps to 0
        if (tk == NSNR - 1) {
            double tot = 0.0;
#pragma unroll
            for (int w = 0; w < NACC; w++) { tot += g_acc[w]; g_acc[w] = 0.0; }
            out[0] = (float)tot;
        }
    }
}

// ---------------------------------------------------------------------------
extern "C" void kernel_launch(void* const* d_in, const int* in_sizes, int n_in,
                              void* d_out, int out_size)
{
    const float* f   = (const float*)d_in[0];
    const float* obs = (const float*)d_in[1];
    const float* t   = (const float*)d_in[2];

    wasserstein_kernel<<<NSNR, TPB>>>(f, obs, t, (float*)d_out);
}

// round 15
// speedup vs baseline: 1.2465x; 1.2465x over previous
#include <cuda_runtime.h>
#include <math.h>
#include <stdint.h>

#define NSNR 2048
#define NT   4096
#define NP   100
#define NI   99
#define TPB  256
#define NC   (NT / 4)      // 1024 chunks of 4 elements
#define CPT  (NC / TPB)    // 4 chunks per thread
#define NWARP (TPB / 32)
#define NACC 32
#define BHW  12            // inverse band half-width (r^13 ~ 3.6e-8)
#define BW   (2 * BHW + 1) // 25

__device__ double       g_acc[NACC];   // zero-init; reset by last row each run
__device__ unsigned int g_ticket;      // self-resetting via atomicInc wrap

// ---------------------------------------------------------------------------
// Banded rows of inv(tri(1,4,1)) (n=98), compile-time double Thomas.
// Stored transposed: w[d][i] = inv[i][i + d - BHW].
// ---------------------------------------------------------------------------
struct WT { float w[BW][NP]; };
static constexpr WT make_wt() {
    WT out{};
    for (int i = 0; i < 98; i++) {
        double cp[98] = {}, dp[98] = {};
        double c = 0.25;
        cp[0] = c;
        dp[0] = (i == 0 ? 1.0 : 0.0) * 0.25;
        for (int j = 1; j < 98; j++) {
            c = 1.0 / (4.0 - cp[j - 1]);
            cp[j] = c;
            double r = (j == i ? 1.0 : 0.0);
            dp[j] = (r - dp[j - 1]) * c;
        }
        double x = dp[97];
        {
            int d = 97 - i + BHW;
            if (d >= 0 && d < BW) out.w[d][i] = (float)x;
        }
        for (int j = 96; j >= 0; j--) {
            x = dp[j] - cp[j] * x;
            int d = j - i + BHW;
            if (d >= 0 && d < BW) out.w[d][i] = (float)x;
        }
    }
    return out;
}
__device__ constexpr WT d_wt = make_wt();

// Block-wide exclusive scan of one float per thread. Contains __syncthreads.
__device__ __forceinline__ float block_scan_excl(float v, float* warp_sums, float* total) {
    int lane = threadIdx.x & 31, wid = threadIdx.x >> 5;
    float x = v;
#pragma unroll
    for (int o = 1; o < 32; o <<= 1) {
        float y = __shfl_up_sync(0xffffffffu, x, o);
        if (lane >= o) x += y;
    }
    if (lane == 31) warp_sums[wid] = x;
    __syncthreads();
    if (wid == 0) {
        float w = (lane < NWARP) ? warp_sums[lane] : 0.0f;
#pragma unroll
        for (int o = 1; o < NWARP; o <<= 1) {
            float y = __shfl_up_sync(0xffffffffu, w, o);
            if (lane >= o) w += y;
        }
        if (lane < NWARP) warp_sums[lane] = w;
    }
    __syncthreads();
    float excl = (x - v) + (wid ? warp_sums[wid - 1] : 0.0f);
    *total = warp_sums[NWARP - 1];
    return excl;
}

// ---------------------------------------------------------------------------
// Striped load of |src| + two-level PLAIN prefix scan of |y| chunk sums.
// Also publishes y[0], y[NT-1] into sEnds under the scan's own syncs.
// ---------------------------------------------------------------------------
__device__ __forceinline__ void chunk_scan(
    const float4* __restrict__ src4,
    float fa[CPT][4], float pfx[CPT],
    float* sCh, float* warp_sums, float* sEnds, float* Ptot)
{
    const int tid = threadIdx.x;
#pragma unroll
    for (int i = 0; i < CPT; i++) {
        float4 v = src4[tid + TPB * i];
        fa[i][0] = fabsf(v.x);
        fa[i][1] = fabsf(v.y);
        fa[i][2] = fabsf(v.z);
        fa[i][3] = fabsf(v.w);
        sCh[tid + TPB * i] = ((fa[i][0] + fa[i][1]) + fa[i][2]) + fa[i][3];
    }
    if (tid == 0)       sEnds[0] = fa[0][0];          // y[0]
    if (tid == TPB - 1) sEnds[1] = fa[CPT - 1][3];    // y[NT-1]
    __syncthreads();

    float4 g4 = reinterpret_cast<float4*>(sCh)[tid];
    float local = ((g4.x + g4.y) + g4.z) + g4.w;
    float total;
    float excl = block_scan_excl(local, warp_sums, &total);
    float4 p4;
    p4.x = excl;
    p4.y = p4.x + g4.x;
    p4.z = p4.y + g4.y;
    p4.w = p4.z + g4.z;
    reinterpret_cast<float4*>(sCh)[tid] = p4;
    __syncthreads();

#pragma unroll
    for (int i = 0; i < CPT; i++) pfx[i] = sCh[tid + TPB * i];
    *Ptot = total;
}

// ---------------------------------------------------------------------------
__global__ void __launch_bounds__(TPB, 8) wasserstein_kernel(
    const float* __restrict__ f, const float* __restrict__ obs,
    const float* __restrict__ t, float* __restrict__ out)
{
    __shared__ float  sCDF[NT];          // obs CDF for search (16 KB)
    __shared__ float  sCh[NC];           // chunk sums / prefixes (4 KB)
    __shared__ float4 scf4[NP];          // u-domain spline coeffs
    __shared__ float  sQ[NP];
    __shared__ float  sM[NP];
    __shared__ float  srhs[98 + 2 * BHW];// zero-padded rhs for banded solve
    __shared__ float  warp_sums[NWARP];
    __shared__ float  red[NWARP];
    __shared__ float  sEnds[2];

    const int   row = blockIdx.x;
    const int   tid = threadIdx.x;
    const float dt  = t[1] - t[0];
    const float hd  = 0.5f * dt;

    // zero rhs pads (never overwritten afterwards)
    if (tid < BHW) { srhs[tid] = 0.0f; srhs[98 + BHW + tid] = 0.0f; }

    float fa[CPT][4], pfx[CPT];
    float Ptot;

    // ============ Phase A: obs -> spline coefficients ============
    chunk_scan(reinterpret_cast<const float4*>(obs + (size_t)row * NT),
               fa, pfx, sCh, warp_sums, sEnds, &Ptot);

    const float y0A = sEnds[0];
    const float totalA = dt * Ptot - hd * (y0A + sEnds[1]);

    // element CDF via closed form: S = base + hd*(r_k + r_{k-1})
#pragma unroll
    for (int i = 0; i < CPT; i++) {
        int c = tid + TPB * i;
        float base = dt * pfx[i] - hd * y0A;
        float4 o;
        float rprev = 0.0f, rr = fa[i][0];
        o.x = fmaf(hd, rr + rprev, base); rprev = rr; rr += fa[i][1];
        o.y = fmaf(hd, rr + rprev, base); rprev = rr; rr += fa[i][2];
        o.z = fmaf(hd, rr + rprev, base); rprev = rr; rr += fa[i][3];
        o.w = fmaf(hd, rr + rprev, base);
        reinterpret_cast<float4*>(sCDF)[c] = o;
    }
    __syncthreads();

    // inverse CDF at 100 quantiles (interpolation + bisection hybrid)
    if (tid < NP) {
        float target = ((float)tid / 99.0f) * totalA;
        int lo = 0, hi = NT - 1;
        float Slo = 0.0f, Shi = totalA;
        int iter = 0;
        while (hi - lo > 1) {
            int mid;
            float den = Shi - Slo;
            if ((iter & 1) == 0 && den > 0.0f) {
                float frac = (target - Slo) / den;
                mid = lo + 1 + (int)(frac * (float)(hi - lo - 1));
                mid = min(max(mid, lo + 1), hi - 1);
            } else {
                mid = (lo + hi) >> 1;
            }
            float Sm = sCDF[mid];
            if (Sm <= target) { lo = mid; Slo = Sm; }
            else              { hi = mid; Shi = Sm; }
            iter++;
        }
        if (sCDF[hi] <= target) lo = hi;   // target == total case
        int j = min(lo, NT - 2);
        float Sj  = sCDF[j];
        float den = sCDF[j + 1] - Sj;
        float q = (float)j * dt;
        if (den > 0.0f) q += (target - Sj) * dt / den;
        sQ[tid] = q;
    }
    __syncthreads();

    // rhs for natural cubic spline (98 interior rows)
    if (tid < 98) {
        const float S6 = 6.0f * 9801.0f;   // 6 / h^2
        srhs[BHW + tid] = S6 * (sQ[tid + 2] - 2.0f * sQ[tid + 1] + sQ[tid]);
    }
    __syncthreads();

    // banded-inverse parallel solve: M_int[i] = sum_d w[d][i]*rhs[i+d-BHW]
    if (tid < 98) {
        float m = 0.0f;
#pragma unroll
        for (int d = 0; d < BW; d++)
            m = fmaf(d_wt.w[d][tid], srhs[tid + d], m);
        sM[tid + 1] = m;
    }
    if (tid == 98) sM[0] = 0.0f;
    if (tid == 99) sM[NP - 1] = 0.0f;
    __syncthreads();

    // u-domain spline coefficients: val = a + du*(b' + du*(c' + du*d')),
    // u = S * (99/T), du = u - idx.  (b'=b*H, c'=c*H^2, d'=d*H^3)
    if (tid < NI) {
        const float H2 = 1.0f / 9801.0f;
        float Mi = sM[tid], Mi1 = sM[tid + 1];
        float4 c;
        c.x = sQ[tid];
        c.y = (sQ[tid + 1] - sQ[tid]) - H2 * (2.0f * Mi + Mi1) * (1.0f / 6.0f);
        c.z = Mi * 0.5f * H2;
        c.w = (Mi1 - Mi) * H2 * (1.0f / 6.0f);
        scf4[tid] = c;
    }
    __syncthreads();

    // ============ Phase B: f -> loss contribution ============
    chunk_scan(reinterpret_cast<const float4*>(f + (size_t)row * NT),
               fa, pfx, sCh, warp_sums, sEnds, &Ptot);

    const float y0B = sEnds[0];
    const float totalB = dt * Ptot - hd * (y0B + sEnds[1]);
    const float invT   = 1.0f / totalB;
    const float invT99 = 99.0f * invT;

    float gsum = 0.0f;
    float gFirst = 0.0f, gLast = 0.0f;
#pragma unroll
    for (int i = 0; i < CPT; i++) {
        int c = tid + TPB * i;
        float base = dt * pfx[i] - hd * y0B;
        float rprev = 0.0f, rr = 0.0f;
#pragma unroll
        for (int k = 0; k < 4; k++) {
            int j = 4 * c + k;
            rr += fa[i][k];
            float S = fmaf(hd, rr + rprev, base);
            rprev = rr;

            float u = fminf(S * invT99, 99.0f);
            int idx = min((int)u, NI - 1);
            float du = u - (float)idx;
            float4 cf = scf4[idx];
            float val = cf.x + du * (cf.y + du * (cf.z + du * cf.w));
            float diff = (float)j * dt - val;
            float g = diff * diff * fa[i][k];
            gsum += g;
            if (i == 0 && k == 0) gFirst = g;        // j==0 (tid==0 only)
            if (i == CPT - 1 && k == 3) gLast = g;   // j==NT-1 (tid==255 only)
        }
    }
    if (tid == 0)       gsum -= 0.5f * gFirst;
    if (tid == TPB - 1) gsum -= 0.5f * gLast;

#pragma unroll
    for (int o = 16; o; o >>= 1) gsum += __shfl_down_sync(0xffffffffu, gsum, o);
    if ((tid & 31) == 0) red[tid >> 5] = gsum;
    __syncthreads();

    if (tid == 0) {
        float s = 0.0f;
#pragma unroll
        for (int w = 0; w < NWARP; w++) s += red[w];
        double my = (double)(dt * invT * s);     // invT applied once here
        atomicAdd(&g_acc[row & (NACC - 1)], my);
        __threadfence();
        unsigned tk = atomicInc(&g_ticket, NSNR - 1);   // wraps to 0
        if (tk == NSNR - 1) {
            double tot = 0.0;
#pragma unroll
            for (int w = 0; w < NACC; w++) { tot += g_acc[w]; g_acc[w] = 0.0; }
            out[0] = (float)tot;
        }
    }
}

// ---------------------------------------------------------------------------
extern "C" void kernel_launch(void* const* d_in, const int* in_sizes, int n_in,
                              void* d_out, int out_size)
{
    const float* f   = (const float*)d_in[0];
    const float* obs = (const float*)d_in[1];
    const float* t   = (const float*)d_in[2];

    wasserstein_kernel<<<NSNR, TPB>>>(f, obs, t, (float*)d_out);
}